// round 6
// baseline (speedup 1.0000x reference)
#include <cuda_runtime.h>
#include <cuda_fp16.h>
#include <cstdint>

#define B_ 2
#define T_ 192
#define C_ 512
#define H_ 8
#define D_ 64
#define PROJC (5 * C_)  // 2560

__device__ float g_proj[B_ * T_ * PROJC];
__device__ float g_attn[B_ * T_ * C_];

// ---------------------------------------------------------------------------
// helpers
// ---------------------------------------------------------------------------
__device__ __forceinline__ unsigned f2tf(float f) {
    unsigned r;
    asm("cvt.rna.tf32.f32 %0, %1;" : "=r"(r) : "f"(f));
    return r;
}
__device__ __forceinline__ void mma8(float* c, const unsigned* a,
                                     unsigned b0, unsigned b1) {
    asm volatile(
        "mma.sync.aligned.m16n8k8.row.col.f32.tf32.tf32.f32 "
        "{%0,%1,%2,%3},{%4,%5,%6,%7},{%8,%9},{%0,%1,%2,%3};\n"
        : "+f"(c[0]), "+f"(c[1]), "+f"(c[2]), "+f"(c[3])
        : "r"(a[0]), "r"(a[1]), "r"(a[2]), "r"(a[3]), "r"(b0), "r"(b1));
}
__device__ __forceinline__ void mma16816(float* c, const unsigned* a,
                                         unsigned b0, unsigned b1) {
    asm volatile(
        "mma.sync.aligned.m16n8k16.row.col.f32.f16.f16.f32 "
        "{%0,%1,%2,%3},{%4,%5,%6,%7},{%8,%9},{%0,%1,%2,%3};\n"
        : "+f"(c[0]), "+f"(c[1]), "+f"(c[2]), "+f"(c[3])
        : "r"(a[0]), "r"(a[1]), "r"(a[2]), "r"(a[3]), "r"(b0), "r"(b1));
}
__device__ __forceinline__ unsigned packh2(float lo, float hi) {
    __half2 h = __floats2half2_rn(lo, hi);
    return *(unsigned*)&h;
}

// ---------------------------------------------------------------------------
// tf32 tensor-core GEMM + bias: C[M,N] = A[M,K] @ Bm[K,N] + bias[N]
// 64x64 tile, 128 threads (4 warps, 2x2), K-step 16, reg-prefetch pipeline.
// M,N divisible by 64; K divisible by 16.
// ---------------------------------------------------------------------------
__global__ __launch_bounds__(128) void gemm_tc_kernel(
    const float* __restrict__ A, const float* __restrict__ Bm,
    const float* __restrict__ bias, float* __restrict__ C,
    int M, int N, int K)
{
    __shared__ float As[64][20];   // tf32 bits, row-major [m][k]
    __shared__ float Bs[16][72];   // tf32 bits, [k][n]

    const int t    = threadIdx.x;
    const int lane = t & 31;
    const int w    = t >> 5;
    const int grp  = lane >> 2;
    const int tid4 = lane & 3;
    const int wm   = w & 1;
    const int wn   = w >> 1;
    const int row0 = blockIdx.y * 64;
    const int col0 = blockIdx.x * 64;

    // loader indices
    const int ar = t >> 2;             // 0..31 (A rows; +32 second)
    const int ac = (t & 3) << 2;       // A col4
    const int br = t >> 4;             // 0..7 (B rows; +8 second)
    const int bc = (t & 15) << 2;      // B col4

    float4 pa0 = *(const float4*)&A[(size_t)(row0 + ar) * K + ac];
    float4 pa1 = *(const float4*)&A[(size_t)(row0 + ar + 32) * K + ac];
    float4 pb0 = *(const float4*)&Bm[(size_t)br * N + col0 + bc];
    float4 pb1 = *(const float4*)&Bm[(size_t)(br + 8) * N + col0 + bc];

    float c[2][4][4] = {};

    for (int kt = 0; kt < K; kt += 16) {
        // store staged tiles (converted to tf32)
        As[ar][ac + 0]      = __uint_as_float(f2tf(pa0.x));
        As[ar][ac + 1]      = __uint_as_float(f2tf(pa0.y));
        As[ar][ac + 2]      = __uint_as_float(f2tf(pa0.z));
        As[ar][ac + 3]      = __uint_as_float(f2tf(pa0.w));
        As[ar + 32][ac + 0] = __uint_as_float(f2tf(pa1.x));
        As[ar + 32][ac + 1] = __uint_as_float(f2tf(pa1.y));
        As[ar + 32][ac + 2] = __uint_as_float(f2tf(pa1.z));
        As[ar + 32][ac + 3] = __uint_as_float(f2tf(pa1.w));
        {
            float4 v0, v1;
            v0.x = __uint_as_float(f2tf(pb0.x)); v0.y = __uint_as_float(f2tf(pb0.y));
            v0.z = __uint_as_float(f2tf(pb0.z)); v0.w = __uint_as_float(f2tf(pb0.w));
            v1.x = __uint_as_float(f2tf(pb1.x)); v1.y = __uint_as_float(f2tf(pb1.y));
            v1.z = __uint_as_float(f2tf(pb1.z)); v1.w = __uint_as_float(f2tf(pb1.w));
            *(float4*)&Bs[br][bc]     = v0;
            *(float4*)&Bs[br + 8][bc] = v1;
        }
        __syncthreads();

        if (kt + 16 < K) {
            pa0 = *(const float4*)&A[(size_t)(row0 + ar) * K + kt + 16 + ac];
            pa1 = *(const float4*)&A[(size_t)(row0 + ar + 32) * K + kt + 16 + ac];
            pb0 = *(const float4*)&Bm[(size_t)(kt + 16 + br) * N + col0 + bc];
            pb1 = *(const float4*)&Bm[(size_t)(kt + 16 + br + 8) * N + col0 + bc];
        }

        #pragma unroll
        for (int kk = 0; kk < 2; kk++) {
            const int k8 = kk << 3;
            unsigned a[2][4];
            #pragma unroll
            for (int mt = 0; mt < 2; mt++) {
                int r = (wm << 5) + (mt << 4) + grp;
                a[mt][0] = __float_as_uint(As[r][k8 + tid4]);
                a[mt][1] = __float_as_uint(As[r + 8][k8 + tid4]);
                a[mt][2] = __float_as_uint(As[r][k8 + tid4 + 4]);
                a[mt][3] = __float_as_uint(As[r + 8][k8 + tid4 + 4]);
            }
            #pragma unroll
            for (int n = 0; n < 4; n++) {
                int cc = (wn << 5) + (n << 3) + grp;
                unsigned b0 = __float_as_uint(Bs[k8 + tid4][cc]);
                unsigned b1 = __float_as_uint(Bs[k8 + tid4 + 4][cc]);
                mma8(c[0][n], a[0], b0, b1);
                mma8(c[1][n], a[1], b0, b1);
            }
        }
        __syncthreads();
    }

    // epilogue
    #pragma unroll
    for (int mt = 0; mt < 2; mt++) {
        #pragma unroll
        for (int n = 0; n < 4; n++) {
            int row = row0 + (wm << 5) + (mt << 4) + grp;
            int col = col0 + (wn << 5) + (n << 3) + (tid4 << 1);
            float2 bv = *(const float2*)&bias[col];
            float2 o0 = make_float2(c[mt][n][0] + bv.x, c[mt][n][1] + bv.y);
            float2 o1 = make_float2(c[mt][n][2] + bv.x, c[mt][n][3] + bv.y);
            *(float2*)&C[(size_t)row * N + col]       = o0;
            *(float2*)&C[(size_t)(row + 8) * N + col] = o1;
        }
    }
}

// ---------------------------------------------------------------------------
// Fused two-simplicial attention, fp16 mma, register E, fp16 U-partials,
// 2 blocks/SM, software-pipelined K1/V1 loads.
// ---------------------------------------------------------------------------

#define OFF_Q    0        // 512   Qs[8][64] fp32 (prescaled)
#define OFF_K1   512      // 512   K1s[8][64] fp32
#define OFF_V1   1024     // 512   V1s[8][64] fp32
#define OFF_ACC  1536     // 512   accS[8][64] fp32
#define OFF_SM   2048     // 8
#define OFF_SZ   2056     // 8
#define OFF_SAL  2064     // 8
#define OFF_RM   2072     // 32    redM[4][8]
#define OFF_RZ   2104     // 32    redZ[4][8]
#define OFF_PH   2144     // 2304  Ph[64][36]  half2 words
#define OFF_K2H  4448     // 6912  K2h[192][36] half2 words (d-pairs)
#define OFF_V2H  11360    // 6912  V2h[96][72]  half2 words (k-pairs x d)
#define OFF_UH   18272    // 9216  Uh[4][64][36] half2 words
#define SMEM_FLOATS 27488  // 109,952 B

__global__ __launch_bounds__(256, 2) void attn_kernel(
    const float* __restrict__ proj, float* __restrict__ outp)
{
    extern __shared__ float sm[];
    float* Qs   = sm + OFF_Q;
    float* K1s  = sm + OFF_K1;
    float* V1s  = sm + OFF_V1;
    float* accS = sm + OFF_ACC;
    float* sM   = sm + OFF_SM;
    float* sZ   = sm + OFF_SZ;
    float* sAl  = sm + OFF_SAL;
    float* redM = sm + OFF_RM;
    float* redZ = sm + OFF_RZ;
    unsigned* Ph  = (unsigned*)(sm + OFF_PH);
    unsigned* K2h = (unsigned*)(sm + OFF_K2H);
    unsigned* V2h = (unsigned*)(sm + OFF_V2H);
    unsigned* Uh  = (unsigned*)(sm + OFF_UH);

    const int t    = threadIdx.x;
    const int lane = t & 31;
    const int w    = t >> 5;
    const int grp  = lane >> 2;
    const int tid4 = lane & 3;
    const int b    = blockIdx.z;
    const int h    = blockIdx.y;
    const int i0   = blockIdx.x * 8;

    const float* base = proj + (size_t)b * T_ * PROJC + h * D_;
    // proj row: q:0  k1:C_  v1:2C_  k2:3C_  v2:4C_

    // K1/V1 pipeline loader role
    const int ttp  = t & 127;
    const int jjp  = ttp >> 4;
    const int d4p  = (ttp & 15) << 2;
    const float* pfbase = base + (size_t)jjp * PROJC +
                          (t < 128 ? C_ : 2 * C_) + d4p;
    float* pfdst = (t < 128 ? K1s : V1s) + (jjp << 6) + d4p;

    // ---- init ----
    float4 preg = *(const float4*)pfbase;   // tile 0
    for (int idx = t; idx < 512; idx += 256) {
        int r = idx >> 6, d = idx & 63;
        Qs[idx]   = base[(size_t)(i0 + r) * PROJC + d] * 0.125f;
        accS[idx] = 0.f;
    }
    if (t < 8) { sM[t] = -3.0e38f; sZ[t] = 0.f; sAl[t] = 0.f; }
    for (int idx = t; idx < 192 * 32; idx += 256) {
        int k = idx >> 5, p = idx & 31;
        float2 v = *(const float2*)&base[(size_t)k * PROJC + 3 * C_ + 2 * p];
        K2h[k * 36 + p] = packh2(v.x, v.y);
    }
    for (int idx = t; idx < 96 * 64; idx += 256) {
        int pr = idx >> 6, d = idx & 63;
        float lo = base[(size_t)(2 * pr)     * PROJC + 4 * C_ + d];
        float hi = base[(size_t)(2 * pr + 1) * PROJC + 4 * C_ + d];
        V2h[pr * 72 + d] = packh2(lo, hi);
    }
    __syncthreads();

    const int wm = w & 1;
    const int wn = w >> 1;

    for (int jt = 0; jt < T_; jt += 8) {
        // ---- (0) commit staged K1/V1 for THIS tile ----
        *(float4*)pfdst = preg;
        __syncthreads();
        // prefetch NEXT tile (lands during this iteration)
        if (jt + 8 < T_)
            preg = *(const float4*)(pfbase + (size_t)(jt + 8) * PROJC);

        // ---- (1) P build: Ph[m][d-pair] half2 ----
        #pragma unroll
        for (int l = 0; l < 4; l++) {
            int idx = t + (l << 8);
            int m = idx >> 4, q4 = idx & 15;
            int i = m >> 3, jj = m & 7;
            float4 qv = *(float4*)&Qs[(i << 6) + (q4 << 2)];
            float4 kv = *(float4*)&K1s[(jj << 6) + (q4 << 2)];
            uint2 pk;
            pk.x = packh2(qv.x * kv.x, qv.y * kv.y);
            pk.y = packh2(qv.z * kv.z, qv.w * kv.w);
            *(uint2*)&Ph[m * 36 + (q4 << 1)] = pk;
        }
        __syncthreads();

        // ---- (2) GEMM1: S[64x192] ----
        float c1[2][6][4] = {};
        {
            const int raBase = (wm << 5) + grp;
            #pragma unroll
            for (int kk = 0; kk < 4; kk++) {
                unsigned A[2][4];
                #pragma unroll
                for (int a = 0; a < 2; a++) {
                    int ra = raBase + (a << 4);
                    A[a][0] = Ph[ra * 36 + (kk << 3) + tid4];
                    A[a][1] = Ph[(ra + 8) * 36 + (kk << 3) + tid4];
                    A[a][2] = Ph[ra * 36 + (kk << 3) + 4 + tid4];
                    A[a][3] = Ph[(ra + 8) * 36 + (kk << 3) + 4 + tid4];
                }
                #pragma unroll
                for (int n = 0; n < 6; n++) {
                    int row = wn * 48 + (n << 3) + grp;
                    unsigned b0 = K2h[row * 36 + (kk << 3) + tid4];
                    unsigned b1 = K2h[row * 36 + (kk << 3) + 4 + tid4];
                    mma16816(c1[0][n], A[0], b0, b1);
                    mma16816(c1[1][n], A[1], b0, b1);
                }
            }
        }

        // ---- (3) online softmax ----
        float mx[4] = {-3.0e38f, -3.0e38f, -3.0e38f, -3.0e38f};
        #pragma unroll
        for (int a = 0; a < 2; a++)
            #pragma unroll
            for (int n = 0; n < 6; n++) {
                mx[2*a+0] = fmaxf(mx[2*a+0], fmaxf(c1[a][n][0], c1[a][n][1]));
                mx[2*a+1] = fmaxf(mx[2*a+1], fmaxf(c1[a][n][2], c1[a][n][3]));
            }
        #pragma unroll
        for (int s = 0; s < 4; s++)
            #pragma unroll
            for (int off = 16; off > 0; off >>= 1)
                mx[s] = fmaxf(mx[s], __shfl_xor_sync(0xffffffffu, mx[s], off));
        if (lane == 0) {
            #pragma unroll
            for (int s = 0; s < 4; s++)
                redM[(wn << 3) + (wm << 2) + s] = mx[s];
        }
        __syncthreads();

        float Mnew[4];
        #pragma unroll
        for (int s = 0; s < 4; s++) {
            int i = (wm << 2) + s;
            float m0 = sM[i];
            #pragma unroll
            for (int q = 0; q < 4; q++) m0 = fmaxf(m0, redM[(q << 3) + i]);
            Mnew[s] = m0;
        }

        unsigned ea[2][3][4];
        float zs[4] = {0.f, 0.f, 0.f, 0.f};
        #pragma unroll
        for (int a = 0; a < 2; a++)
            #pragma unroll
            for (int n = 0; n < 6; n++) {
                float e0 = __expf(c1[a][n][0] - Mnew[2*a+0]);
                float e1 = __expf(c1[a][n][1] - Mnew[2*a+0]);
                float e2 = __expf(c1[a][n][2] - Mnew[2*a+1]);
                float e3 = __expf(c1[a][n][3] - Mnew[2*a+1]);
                zs[2*a+0] += e0 + e1;
                zs[2*a+1] += e2 + e3;
                unsigned p0 = packh2(e0, e1);
                unsigned p1 = packh2(e2, e3);
                if (n & 1) { ea[a][n >> 1][2] = p0; ea[a][n >> 1][3] = p1; }
                else       { ea[a][n >> 1][0] = p0; ea[a][n >> 1][1] = p1; }
            }
        #pragma unroll
        for (int s = 0; s < 4; s++)
            #pragma unroll
            for (int off = 16; off > 0; off >>= 1)
                zs[s] += __shfl_xor_sync(0xffffffffu, zs[s], off);
        if (lane == 0) {
            #pragma unroll
            for (int s = 0; s < 4; s++)
                redZ[(wn << 3) + (wm << 2) + s] = zs[s];
        }
        __syncthreads();

        if (t < 8) {
            float Mo = sM[t];
            float Mn = Mo;
            #pragma unroll
            for (int q = 0; q < 4; q++) Mn = fmaxf(Mn, redM[(q << 3) + t]);
            float alpha = __expf(Mo - Mn);
            float zsum = 0.f;
            #pragma unroll
            for (int q = 0; q < 4; q++) zsum += redZ[(q << 3) + t];
            sZ[t]  = sZ[t] * alpha + zsum;
            sM[t]  = Mn;
            sAl[t] = alpha;
        }

        // ---- (4) GEMM2 partial U (fp16 out), two n-halves to cap regs ----
        #pragma unroll
        for (int nh = 0; nh < 2; nh++) {
            float u[2][4][4] = {};
            #pragma unroll
            for (int kk2 = 0; kk2 < 3; kk2++) {
                int rb = 24 * wn + (kk2 << 3);
                #pragma unroll
                for (int n = 0; n < 4; n++) {
                    int nn = (nh << 2) + n;
                    unsigned b0 = V2h[(rb + tid4) * 72 + (nn << 3) + grp];
                    unsigned b1 = V2h[(rb + 4 + tid4) * 72 + (nn << 3) + grp];
                    mma16816(u[0][n], ea[0][kk2], b0, b1);
                    mma16816(u[1][n], ea[1][kk2], b0, b1);
                }
            }
            unsigned* Uq = Uh + wn * 2304;
            #pragma unroll
            for (int a = 0; a < 2; a++)
                #pragma unroll
                for (int n = 0; n < 4; n++) {
                    int nn = (nh << 2) + n;
                    int r  = (wm << 5) + (a << 4) + grp;
                    int cw = (nn << 2) + tid4;
                    Uq[r * 36 + cw]       = packh2(u[a][n][0], u[a][n][1]);
                    Uq[(r + 8) * 36 + cw] = packh2(u[a][n][2], u[a][n][3]);
                }
        }
        __syncthreads();

        // ---- (5) epilogue ----
        {
            const int i  = t >> 5;
            float2 acc = *(float2*)&accS[(i << 6) + (lane << 1)];
            float al = sAl[i];
            acc.x *= al; acc.y *= al;
            #pragma unroll
            for (int jj = 0; jj < 8; jj++) {
                int m = (i << 3) + jj;
                float sx = 0.f, sy = 0.f;
                #pragma unroll
                for (int q = 0; q < 4; q++) {
                    unsigned uw = Uh[q * 2304 + m * 36 + lane];
                    float2 f = __half22float2(*(__half2*)&uw);
                    sx += f.x; sy += f.y;
                }
                float2 v1 = *(float2*)&V1s[(jj << 6) + (lane << 1)];
                acc.x += v1.x * sx;
                acc.y += v1.y * sy;
            }
            *(float2*)&accS[(i << 6) + (lane << 1)] = acc;
        }
        __syncthreads();
    }

    // ---- finalize ----
    {
        const int i  = t >> 5;
        float invZ = 1.0f / sZ[i];
        float2 acc = *(float2*)&accS[(i << 6) + (lane << 1)];
        acc.x *= invZ; acc.y *= invZ;
        *(float2*)&outp[(size_t)(b * T_ + i0 + i) * C_ + h * D_ + (lane << 1)] = acc;
    }
}

// ---------------------------------------------------------------------------
extern "C" void kernel_launch(void* const* d_in, const int* in_sizes, int n_in,
                              void* d_out, int out_size)
{
    const float* x     = (const float*)d_in[0];
    const float* W_in  = (const float*)d_in[1];
    const float* b_in  = (const float*)d_in[2];
    const float* W_out = (const float*)d_in[3];
    const float* b_out = (const float*)d_in[4];
    float* y = (float*)d_out;

    float *proj, *attn;
    cudaGetSymbolAddress((void**)&proj, g_proj);
    cudaGetSymbolAddress((void**)&attn, g_attn);

    const size_t SMEM = (size_t)SMEM_FLOATS * sizeof(float);  // 109,952 B
    cudaFuncSetAttribute(attn_kernel,
                         cudaFuncAttributeMaxDynamicSharedMemorySize, (int)SMEM);

    // 1) proj = x @ W_in + b_in : (384,512)@(512,2560)
    dim3 g1(PROJC / 64, (B_ * T_) / 64);
    gemm_tc_kernel<<<g1, 128>>>(x, W_in, b_in, proj, B_ * T_, PROJC, C_);

    // 2) fused attention
    dim3 ga(T_ / 8, H_, B_);
    attn_kernel<<<ga, 256, SMEM>>>(proj, attn);

    // 3) y = attn @ W_out + b_out : (384,512)@(512,512)
    dim3 g2(C_ / 64, (B_ * T_) / 64);
    gemm_tc_kernel<<<g2, 128>>>(attn, W_out, b_out, y, B_ * T_, C_, C_);
}